// round 7
// baseline (speedup 1.0000x reference)
#include <cuda_runtime.h>
#include <cuda_fp16.h>
#include <cstdint>
#include <cstddef>

#define DEVINL __device__ __forceinline__
using u32 = uint32_t;
using ull = unsigned long long;

constexpr int D  = 512;
constexpr int NC = 128;

constexpr int TILE_B  = 16384;             // one 128-row x 128B packed tile
constexpr int V7_STAGE = 3 * TILE_B;       // A(2 tiles) + B(1 tile) = 48KB
constexpr int V7_NST   = 3;
constexpr int V7_SMEM  = V7_NST * V7_STAGE;            // 147456
constexpr int VQ7_SMEM = V7_SMEM + 512 + 4096 + 1024;  // + scn + wb + bidx

__device__ float g_cnorm[NC];
__device__ __align__(128) char g_xsplit[256][16][TILE_B];   // 64 MB
__device__ __align__(128) char g_zsplit[256][16][TILE_B];   // 64 MB
__device__ __align__(128) char g_wsplit[4][16][TILE_B];     // 1 MB
__device__ __align__(128) char g_cbsplit[16][TILE_B];       // 256 KB

// ---------------------------------------------------------------- helpers
DEVINL u32 smem_u32(const void* p) {
    u32 a;
    asm("{ .reg .u64 t; cvta.to.shared.u64 t, %1; cvt.u32.u64 %0, t; }"
        : "=r"(a) : "l"(p));
    return a;
}
DEVINL void ldsm4(u32& r0, u32& r1, u32& r2, u32& r3, u32 a) {
    asm volatile("ldmatrix.sync.aligned.m8n8.x4.shared.b16 {%0,%1,%2,%3}, [%4];"
                 : "=r"(r0), "=r"(r1), "=r"(r2), "=r"(r3) : "r"(a));
}
DEVINL void mma_f16(float c[4], const u32 a[4], const u32 b[2]) {
    asm volatile(
        "mma.sync.aligned.m16n8k16.row.col.f32.f16.f16.f32 "
        "{%0,%1,%2,%3},{%4,%5,%6,%7},{%8,%9},{%0,%1,%2,%3};"
        : "+f"(c[0]), "+f"(c[1]), "+f"(c[2]), "+f"(c[3])
        : "r"(a[0]), "r"(a[1]), "r"(a[2]), "r"(a[3]), "r"(b[0]), "r"(b[1]));
}
DEVINL u32 pack_h2(__half a, __half b) {
    __half2 h = __halves2half2(a, b);
    return *reinterpret_cast<u32*>(&h);
}
DEVINL void fsplit(float x, __half& h, __half& l) {
    h = __float2half_rn(x);
    l = __float2half_rn(x - __half2float(h));
}
DEVINL void cp16(u32 dst, const void* src) {
    asm volatile("cp.async.cg.shared.global [%0], [%1], 16;" :: "r"(dst), "l"(src));
}
DEVINL void cp_commit() { asm volatile("cp.async.commit_group;" ::: "memory"); }
DEVINL void cp_wait1()  { asm volatile("cp.async.wait_group 1;" ::: "memory"); }
DEVINL void cp_wait0()  { asm volatile("cp.async.wait_group 0;" ::: "memory"); }

// split 16 fp32 into 2 hi + 2 lo 16B chunks of a packed tile row.
// hi chunk c at ((c^e)<<4), lo at (((c^4)^e)<<4), e = row&7.
DEVINL void split16(const float4 v[4], char* drow, int c0, int e) {
    #pragma unroll
    for (int c2 = 0; c2 < 2; ++c2) {
        const float f[8] = { v[2*c2].x, v[2*c2].y, v[2*c2].z, v[2*c2].w,
                             v[2*c2+1].x, v[2*c2+1].y, v[2*c2+1].z, v[2*c2+1].w };
        __half hh[8], ll[8];
        #pragma unroll
        for (int j = 0; j < 8; ++j) fsplit(f[j], hh[j], ll[j]);
        uint4 uh = make_uint4(pack_h2(hh[0], hh[1]), pack_h2(hh[2], hh[3]),
                              pack_h2(hh[4], hh[5]), pack_h2(hh[6], hh[7]));
        uint4 ul = make_uint4(pack_h2(ll[0], ll[1]), pack_h2(ll[2], ll[3]),
                              pack_h2(ll[4], ll[5]), pack_h2(ll[6], ll[7]));
        const int c = c0 + c2;
        *(uint4*)(drow + (((c)     ^ e) << 4)) = uh;
        *(uint4*)(drow + (((c ^ 4) ^ e) << 4)) = ul;
    }
}

// ---------------------------------------------------------------- prepass kernels
__global__ void split_x_kernel(const float* __restrict__ X) {
    __shared__ __align__(16) char st[TILE_B];
    const int s = blockIdx.x, rb = blockIdx.y;
    const int tid = threadIdx.x, r = tid >> 1, h = tid & 1;
    const float4* src = (const float4*)(X + (size_t)(rb * 128 + r) * D + s * 32 + h * 16);
    float4 v[4];
    #pragma unroll
    for (int i = 0; i < 4; ++i) v[i] = src[i];
    split16(v, &st[r * 128], h * 2, r & 7);
    __syncthreads();
    char* dst = &g_xsplit[rb][s][0];
    #pragma unroll
    for (int k = 0; k < 4; ++k)
        *(uint4*)(dst + tid * 16 + k * 4096) = *(const uint4*)(st + tid * 16 + k * 4096);
}

__global__ void split_const_kernel(const float* __restrict__ W,
                                   const float* __restrict__ CB) {
    __shared__ __align__(16) char st[TILE_B];
    const int b = blockIdx.x;
    const int tid = threadIdx.x, r = tid >> 1, h = tid & 1;
    if (b < 80) {
        const float* src0;
        char* dst;
        if (b < 64) {
            const int ct = b >> 4, s = b & 15;
            src0 = W + (size_t)(ct * 128 + r) * D + s * 32 + h * 16;
            dst = &g_wsplit[ct][s][0];
        } else {
            const int s = b - 64;
            src0 = CB + (size_t)r * D + s * 32 + h * 16;
            dst = &g_cbsplit[s][0];
        }
        float4 v[4];
        #pragma unroll
        for (int i = 0; i < 4; ++i) v[i] = ((const float4*)src0)[i];
        split16(v, &st[r * 128], h * 2, r & 7);
        __syncthreads();
        #pragma unroll
        for (int k = 0; k < 4; ++k)
            *(uint4*)(dst + tid * 16 + k * 4096) = *(const uint4*)(st + tid * 16 + k * 4096);
    } else {
        const int c = tid >> 1;
        const float4* p = (const float4*)(CB + (size_t)c * D + h * 256);
        float s = 0.f;
        #pragma unroll 4
        for (int k = 0; k < 64; ++k) {
            float4 v = p[k];
            s += v.x * v.x + v.y * v.y + v.z * v.z + v.w * v.w;
        }
        s += __shfl_xor_sync(0xffffffffu, s, 1);
        if (!h) g_cnorm[c] = s;
    }
}

// ---------------------------------------------------------------- per-stage MMA (256x128x32, split-2)
// 8 warps, grid 4m x 2n, warp tile 64x64. A = 256 rows (2 packed tiles), B at +32KB.
DEVINL void stage_mma7(u32 aT, int tid, float acc[4][8][4]) {
    const int lane = tid & 31, w = tid >> 5;
    const int mw = w >> 1, nw = w & 1;
    const int eL = lane & 7;
    const int rA = lane & 15, cAk = lane >> 4;
    const int rBr = ((lane >> 4) << 3) | (lane & 7);
    const int cBk = (lane >> 3) & 1;
    const u32 bT = aT + 2 * TILE_B;

    #pragma unroll
    for (int kk = 0; kk < 2; ++kk) {
        u32 bhi[8][2], blo[8][2];
        const int swB = (kk * 2 + cBk) ^ eL;
        #pragma unroll
        for (int bp = 0; bp < 4; ++bp) {
            const u32 base = bT + (nw * 64 + bp * 16 + rBr) * 128;
            u32 r0, r1, r2, r3;
            ldsm4(r0, r1, r2, r3, base + (swB << 4));
            bhi[bp*2][0] = r0; bhi[bp*2][1] = r1;
            bhi[bp*2+1][0] = r2; bhi[bp*2+1][1] = r3;
            ldsm4(r0, r1, r2, r3, base + ((swB ^ 4) << 4));
            blo[bp*2][0] = r0; blo[bp*2][1] = r1;
            blo[bp*2+1][0] = r2; blo[bp*2+1][1] = r3;
        }
        const int swA = (kk * 2 + cAk) ^ eL;
        #pragma unroll
        for (int mb = 0; mb < 4; ++mb) {
            u32 ahi[4], alo[4];
            const u32 base = aT + (mw * 64 + mb * 16 + rA) * 128;
            ldsm4(ahi[0], ahi[1], ahi[2], ahi[3], base + (swA << 4));
            ldsm4(alo[0], alo[1], alo[2], alo[3], base + ((swA ^ 4) << 4));
            #pragma unroll
            for (int nb = 0; nb < 8; ++nb) {
                mma_f16(acc[mb][nb], ahi, bhi[nb]);
                mma_f16(acc[mb][nb], ahi, blo[nb]);
                mma_f16(acc[mb][nb], alo, bhi[nb]);
            }
        }
    }
}

// ---------------------------------------------------------------- GEMM: Z = X W^T + b (+ split-z emit)
__global__ void __launch_bounds__(256, 1)
gemm_hmma(const float* __restrict__ bias, float* __restrict__ Z)
{
    extern __shared__ char smc[];
    const u32 sb = smem_u32(smc);
    const int tid = threadIdx.x;
    const int ct = blockIdx.x, rbt = blockIdx.y;     // ct fast -> X L2 reuse

    const char* a0 = &g_xsplit[2 * rbt][0][0];
    const char* a1 = &g_xsplit[2 * rbt + 1][0][0];
    const char* bb = &g_wsplit[ct][0][0];

    // thread copies 12x16B at stride 4096: bytes [0,16K)=a0, [16K,32K)=a1, [32K,48K)=B
    #define G_ISSUE(s, buf) do {                                               \
        const u32 _d = sb + (buf) * V7_STAGE + tid * 16;                       \
        const char* _a0 = a0 + (s) * TILE_B + tid * 16;                        \
        const char* _a1 = a1 + (s) * TILE_B + tid * 16;                        \
        const char* _b  = bb + (s) * TILE_B + tid * 16;                        \
        _Pragma("unroll")                                                      \
        for (int _k = 0; _k < 4; ++_k) {                                       \
            cp16(_d + _k * 4096,             _a0 + _k * 4096);                 \
            cp16(_d + (4 + _k) * 4096,       _a1 + _k * 4096);                 \
            cp16(_d + (8 + _k) * 4096,       _b  + _k * 4096);                 \
        }                                                                      \
    } while (0)

    G_ISSUE(0, 0); cp_commit();
    G_ISSUE(1, 1); cp_commit();

    float acc[4][8][4] = {};
    int buf = 0;
    #pragma unroll 1
    for (int s = 0; s < 16; ++s) {
        cp_wait1();
        __syncthreads();
        int b2 = buf + 2; if (b2 >= 3) b2 -= 3;
        if (s + 2 < 16) G_ISSUE(s + 2, b2);
        cp_commit();
        stage_mma7(sb + buf * V7_STAGE, tid, acc);
        if (++buf == 3) buf = 0;
    }
    #undef G_ISSUE

    cp_wait0();
    __syncthreads();

    float* zs = (float*)smc;                         // [128][132] = 67584 B
    char*  scr = smc + 67584;                        // 16 KB scratch
    const int lane = tid & 31, w = tid >> 5;
    const int mw = w >> 1, nw = w & 1;
    const int col0 = ct * 128;

    #pragma unroll 1
    for (int p = 0; p < 2; ++p) {
        if ((mw >> 1) == p) {
            const int mwl = mw & 1;
            #pragma unroll
            for (int nb = 0; nb < 8; ++nb) {
                const int col = nw * 64 + nb * 8 + (lane & 3) * 2;
                const float2 bv = *(const float2*)&bias[col0 + col];
                #pragma unroll
                for (int mb = 0; mb < 4; ++mb) {
                    const int lr = mwl * 64 + mb * 16 + (lane >> 2);
                    *(float2*)&zs[lr * 132 + col] =
                        make_float2(acc[mb][nb][0] + bv.x, acc[mb][nb][1] + bv.y);
                    *(float2*)&zs[(lr + 8) * 132 + col] =
                        make_float2(acc[mb][nb][2] + bv.x, acc[mb][nb][3] + bv.y);
                }
            }
        }
        __syncthreads();

        // coalesced fp32 Z store for this 128-row half
        const int grow0 = rbt * 256 + p * 128;
        #pragma unroll
        for (int it = 0; it < 16; ++it) {
            const int idx = tid + it * 256;          // 4096 float4 slots
            const int rr = idx >> 5, c4 = (idx & 31) * 4;
            float4 v = *(float4*)&zs[rr * 132 + c4];
            *(float4*)&Z[(size_t)(grow0 + rr) * D + col0 + c4] = v;
        }

        // split-z emit for rowblock 2*rbt+p
        const int r = tid >> 1, h = tid & 1, e = r & 7;
        char* zdstBase = &g_zsplit[2 * rbt + p][ct * 4][0];
        #pragma unroll 1
        for (int sl = 0; sl < 4; ++sl) {
            float4 v[4];
            #pragma unroll
            for (int i = 0; i < 4; ++i)
                v[i] = *(float4*)&zs[r * 132 + sl * 32 + h * 16 + i * 4];
            split16(v, scr + r * 128, h * 2, e);
            __syncthreads();
            char* dst = zdstBase + sl * TILE_B;
            #pragma unroll
            for (int k = 0; k < 4; ++k)
                *(uint4*)(dst + tid * 16 + k * 4096) =
                    *(const uint4*)(scr + tid * 16 + k * 4096);
            __syncthreads();
        }
    }
}

// ---------------------------------------------------------------- VQ: dots, argmin, gather
__global__ void __launch_bounds__(256, 1)
vq_hmma(const float* __restrict__ CB, float* __restrict__ Q1, float* __restrict__ Q2)
{
    extern __shared__ char smc[];
    float* scn  = (float*)(smc + V7_SMEM);
    ull*   wb   = (ull*)  (smc + V7_SMEM + 512);
    int*   bidx = (int*)  (smc + V7_SMEM + 512 + 4096);

    const u32 sb = smem_u32(smc);
    const int tid = threadIdx.x;
    const int rbt = blockIdx.x;
    const int row0 = rbt * 256;
    if (tid < NC) scn[tid] = g_cnorm[tid];

    const char* a0 = &g_zsplit[2 * rbt][0][0];
    const char* a1 = &g_zsplit[2 * rbt + 1][0][0];
    const char* bb = &g_cbsplit[0][0];

    #define V_ISSUE(s, buf) do {                                               \
        const u32 _d = sb + (buf) * V7_STAGE + tid * 16;                       \
        const char* _a0 = a0 + (s) * TILE_B + tid * 16;                        \
        const char* _a1 = a1 + (s) * TILE_B + tid * 16;                        \
        const char* _b  = bb + (s) * TILE_B + tid * 16;                        \
        _Pragma("unroll")                                                      \
        for (int _k = 0; _k < 4; ++_k) {                                       \
            cp16(_d + _k * 4096,             _a0 + _k * 4096);                 \
            cp16(_d + (4 + _k) * 4096,       _a1 + _k * 4096);                 \
            cp16(_d + (8 + _k) * 4096,       _b  + _k * 4096);                 \
        }                                                                      \
    } while (0)

    V_ISSUE(0, 0); cp_commit();
    V_ISSUE(1, 1); cp_commit();

    float acc[4][8][4] = {};
    int buf = 0;
    #pragma unroll 1
    for (int s = 0; s < 16; ++s) {
        cp_wait1();
        __syncthreads();
        int b2 = buf + 2; if (b2 >= 3) b2 -= 3;
        if (s + 2 < 16) V_ISSUE(s + 2, b2);
        cp_commit();
        stage_mma7(sb + buf * V7_STAGE, tid, acc);
        if (++buf == 3) buf = 0;
    }
    #undef V_ISSUE

    const int lane = tid & 31, w = tid >> 5;
    const int mw = w >> 1, nw = w & 1;

    #pragma unroll
    for (int mb = 0; mb < 4; ++mb) {
        #pragma unroll
        for (int rh = 0; rh < 2; ++rh) {
            ull best = ~0ull;
            #pragma unroll
            for (int nb = 0; nb < 8; ++nb) {
                #pragma unroll
                for (int j = 0; j < 2; ++j) {
                    const int code = nw * 64 + nb * 8 + (lane & 3) * 2 + j;
                    const float sc = fmaf(-2.f, acc[mb][nb][rh * 2 + j], scn[code]);
                    u32 o = __float_as_uint(sc);
                    o = (o & 0x80000000u) ? ~o : (o | 0x80000000u);
                    const ull key = ((ull)o << 32) | (u32)code;
                    if (key < best) best = key;
                }
            }
            ull t = __shfl_xor_sync(0xffffffffu, best, 1); if (t < best) best = t;
            t     = __shfl_xor_sync(0xffffffffu, best, 2); if (t < best) best = t;
            const int lrow = mw * 64 + mb * 16 + rh * 8 + (lane >> 2);
            if ((lane & 3) == 0) wb[lrow * 2 + nw] = best;
        }
    }
    __syncthreads();

    if (tid < 256) {
        ull m = wb[tid * 2];
        ull a = wb[tid * 2 + 1];
        if (a < m) m = a;
        bidx[tid] = (int)(m & 0xffffffffu);
    }
    __syncthreads();

    for (int rr = w; rr < 256; rr += 8) {
        const int idx = bidx[rr];
        const float4* s4 = (const float4*)(CB + (size_t)idx * D);
        float4* o1 = (float4*)(Q1 + (size_t)(row0 + rr) * D);
        float4* o2 = (float4*)(Q2 + (size_t)(row0 + rr) * D);
        #pragma unroll
        for (int i = lane; i < D / 4; i += 32) {
            const float4 vv = s4[i];
            o1[i] = vv;
            o2[i] = vv;
        }
    }
}

// ---------------------------------------------------------------- launcher
extern "C" void kernel_launch(void* const* d_in, const int* in_sizes, int n_in,
                              void* d_out, int out_size)
{
    const float* x  = (const float*)d_in[0];
    const float* W  = (const float*)d_in[1];
    const float* b  = (const float*)d_in[2];
    const float* cb = (const float*)d_in[3];

    const int M = in_sizes[0] / D;            // 32768

    float* out = (float*)d_out;
    float* q1 = out;
    float* q2 = out + (size_t)M * D;
    float* z  = out + (size_t)2 * M * D;

    split_const_kernel<<<81, 256>>>(W, cb);
    split_x_kernel<<<dim3(16, M / 128), 256>>>(x);

    cudaFuncSetAttribute(gemm_hmma, cudaFuncAttributeMaxDynamicSharedMemorySize, V7_SMEM);
    gemm_hmma<<<dim3(D / 128, M / 256), 256, V7_SMEM>>>(b, z);

    cudaFuncSetAttribute(vq_hmma, cudaFuncAttributeMaxDynamicSharedMemorySize, VQ7_SMEM);
    vq_hmma<<<M / 256, 256, VQ7_SMEM>>>(cb, q1, q2);
}

// round 8
// speedup vs baseline: 1.1583x; 1.1583x over previous
#include <cuda_runtime.h>
#include <cuda_fp16.h>
#include <cstdint>
#include <cstddef>

#define DEVINL __device__ __forceinline__
using u32 = uint32_t;
using ull = unsigned long long;

constexpr int D  = 512;
constexpr int NC = 128;

constexpr int TILE_B   = 16384;            // one 128-row x 128B packed tile (hi|lo)
constexpr int STAGE_B  = 2 * TILE_B;       // A tile + B tile
constexpr int NSTAGE   = 3;
constexpr int LOOP_SMEM = NSTAGE * STAGE_B;            // 98304
constexpr int GEMM_SMEM = 67584 + 2 * TILE_B;          // zs[128][132] + 2 scratch = 100352
constexpr int VQ_SMEM   = LOOP_SMEM + 512 + 4096 + 512;

__device__ float g_cnorm[NC];
__device__ __align__(128) char g_xsplit[256][16][TILE_B];   // 64 MB
__device__ __align__(128) char g_zsplit[256][16][TILE_B];   // 64 MB
__device__ __align__(128) char g_wsplit[4][16][TILE_B];     // 1 MB
__device__ __align__(128) char g_cbsplit[16][TILE_B];       // 256 KB

// ---------------------------------------------------------------- helpers
DEVINL u32 smem_u32(const void* p) {
    u32 a;
    asm("{ .reg .u64 t; cvta.to.shared.u64 t, %1; cvt.u32.u64 %0, t; }"
        : "=r"(a) : "l"(p));
    return a;
}
DEVINL void ldsm4(u32& r0, u32& r1, u32& r2, u32& r3, u32 a) {
    asm volatile("ldmatrix.sync.aligned.m8n8.x4.shared.b16 {%0,%1,%2,%3}, [%4];"
                 : "=r"(r0), "=r"(r1), "=r"(r2), "=r"(r3) : "r"(a));
}
DEVINL void mma_f16(float c[4], const u32 a[4], const u32 b[2]) {
    asm volatile(
        "mma.sync.aligned.m16n8k16.row.col.f32.f16.f16.f32 "
        "{%0,%1,%2,%3},{%4,%5,%6,%7},{%8,%9},{%0,%1,%2,%3};"
        : "+f"(c[0]), "+f"(c[1]), "+f"(c[2]), "+f"(c[3])
        : "r"(a[0]), "r"(a[1]), "r"(a[2]), "r"(a[3]), "r"(b[0]), "r"(b[1]));
}
DEVINL u32 pack_h2(__half a, __half b) {
    __half2 h = __halves2half2(a, b);
    return *reinterpret_cast<u32*>(&h);
}
DEVINL void fsplit(float x, __half& h, __half& l) {
    h = __float2half_rn(x);
    l = __float2half_rn(x - __half2float(h));
}
DEVINL void cp16(u32 dst, const void* src) {
    asm volatile("cp.async.cg.shared.global [%0], [%1], 16;" :: "r"(dst), "l"(src));
}
DEVINL void cp_commit() { asm volatile("cp.async.commit_group;" ::: "memory"); }
DEVINL void cp_wait1()  { asm volatile("cp.async.wait_group 1;" ::: "memory"); }
DEVINL void cp_wait0()  { asm volatile("cp.async.wait_group 0;" ::: "memory"); }

// split 16 fp32 into 2 hi + 2 lo 16B chunks of a packed tile row.
// hi chunk c at ((c^e)<<4), lo at (((c^4)^e)<<4), e = row&7.
DEVINL void split16(const float4 v[4], char* drow, int c0, int e) {
    #pragma unroll
    for (int c2 = 0; c2 < 2; ++c2) {
        const float f[8] = { v[2*c2].x, v[2*c2].y, v[2*c2].z, v[2*c2].w,
                             v[2*c2+1].x, v[2*c2+1].y, v[2*c2+1].z, v[2*c2+1].w };
        __half hh[8], ll[8];
        #pragma unroll
        for (int j = 0; j < 8; ++j) fsplit(f[j], hh[j], ll[j]);
        uint4 uh = make_uint4(pack_h2(hh[0], hh[1]), pack_h2(hh[2], hh[3]),
                              pack_h2(hh[4], hh[5]), pack_h2(hh[6], hh[7]));
        uint4 ul = make_uint4(pack_h2(ll[0], ll[1]), pack_h2(ll[2], ll[3]),
                              pack_h2(ll[4], ll[5]), pack_h2(ll[6], ll[7]));
        const int c = c0 + c2;
        *(uint4*)(drow + (((c)     ^ e) << 4)) = uh;
        *(uint4*)(drow + (((c ^ 4) ^ e) << 4)) = ul;
    }
}

// ---------------------------------------------------------------- merged prepass
// blocks [0,4096): x split tiles. [4096,4160): W. [4160,4176): CB. 4176: cnorm.
__global__ void prepass_kernel(const float* __restrict__ X,
                               const float* __restrict__ W,
                               const float* __restrict__ CB) {
    __shared__ __align__(16) char st[TILE_B];
    const int b = blockIdx.x;
    const int tid = threadIdx.x, r = tid >> 1, h = tid & 1;

    if (b == 4176) {
        const int c = tid >> 1;
        const float4* p = (const float4*)(CB + (size_t)c * D + h * 256);
        float s = 0.f;
        #pragma unroll 4
        for (int k = 0; k < 64; ++k) {
            float4 v = p[k];
            s += v.x * v.x + v.y * v.y + v.z * v.z + v.w * v.w;
        }
        s += __shfl_xor_sync(0xffffffffu, s, 1);
        if (!h) g_cnorm[c] = s;
        return;
    }

    const float* src0;
    char* dst;
    if (b < 4096) {
        const int rb = b >> 4, s = b & 15;
        src0 = X + (size_t)(rb * 128 + r) * D + s * 32 + h * 16;
        dst = &g_xsplit[rb][s][0];
    } else if (b < 4160) {
        const int bb = b - 4096;
        const int ct = bb >> 4, s = bb & 15;
        src0 = W + (size_t)(ct * 128 + r) * D + s * 32 + h * 16;
        dst = &g_wsplit[ct][s][0];
    } else {
        const int s = b - 4160;
        src0 = CB + (size_t)r * D + s * 32 + h * 16;
        dst = &g_cbsplit[s][0];
    }
    float4 v[4];
    #pragma unroll
    for (int i = 0; i < 4; ++i) v[i] = ((const float4*)src0)[i];
    split16(v, &st[r * 128], h * 2, r & 7);
    __syncthreads();
    #pragma unroll
    for (int k = 0; k < 4; ++k)
        *(uint4*)(dst + tid * 16 + k * 4096) = *(const uint4*)(st + tid * 16 + k * 4096);
}

// ---------------------------------------------------------------- per-stage MMA (128x128x32, split-2)
DEVINL void stage_mma(u32 aT, int tid, float acc[4][4][4]) {
    const int lane = tid & 31, w = tid >> 5;
    const int mw = w >> 2, nw = w & 3;
    const int eL = lane & 7;
    const int rA = lane & 15, cAk = lane >> 4;
    const int rB0 = nw * 32 + ((lane >> 4) << 3) + (lane & 7);
    const int cBk = (lane >> 3) & 1;
    const u32 bT = aT + TILE_B;

    #pragma unroll
    for (int kk = 0; kk < 2; ++kk) {
        u32 ahi[4][4], alo[4][4], bhi[4][2], blo[4][2];
        const int swA = (kk * 2 + cAk) ^ eL;
        #pragma unroll
        for (int mb = 0; mb < 4; ++mb) {
            const u32 base = aT + (mw * 64 + mb * 16 + rA) * 128;
            ldsm4(ahi[mb][0], ahi[mb][1], ahi[mb][2], ahi[mb][3], base + (swA << 4));
            ldsm4(alo[mb][0], alo[mb][1], alo[mb][2], alo[mb][3], base + ((swA ^ 4) << 4));
        }
        const int swB = (kk * 2 + cBk) ^ eL;
        #pragma unroll
        for (int bp = 0; bp < 2; ++bp) {
            const u32 base = bT + (rB0 + bp * 16) * 128;
            u32 r0, r1, r2, r3;
            ldsm4(r0, r1, r2, r3, base + (swB << 4));
            bhi[bp*2][0] = r0; bhi[bp*2][1] = r1;
            bhi[bp*2+1][0] = r2; bhi[bp*2+1][1] = r3;
            ldsm4(r0, r1, r2, r3, base + ((swB ^ 4) << 4));
            blo[bp*2][0] = r0; blo[bp*2][1] = r1;
            blo[bp*2+1][0] = r2; blo[bp*2+1][1] = r3;
        }
        #pragma unroll
        for (int mb = 0; mb < 4; ++mb)
            #pragma unroll
            for (int nb = 0; nb < 4; ++nb) {
                mma_f16(acc[mb][nb], ahi[mb], bhi[nb]);
                mma_f16(acc[mb][nb], ahi[mb], blo[nb]);
                mma_f16(acc[mb][nb], alo[mb], bhi[nb]);
            }
    }
}

// ---------------------------------------------------------------- GEMM: Z = X W^T + b (+ split-z emit)
__global__ void __launch_bounds__(256, 2)
gemm_hmma(const float* __restrict__ bias, float* __restrict__ Z)
{
    extern __shared__ char smc[];
    const u32 sb = smem_u32(smc);
    const int tid = threadIdx.x;
    const int ct = blockIdx.x, rb = blockIdx.y;      // ct fast -> X L2 reuse
    const int li = tid & 127;

    const char* srcBase = (tid < 128) ? &g_xsplit[rb][0][0] : &g_wsplit[ct][0][0];
    const u32 dstBase = ((tid < 128) ? 0u : (u32)TILE_B) + li * 16;

    #define G_ISSUE(s, buf) do {                                              \
        const char* _src = srcBase + (s) * TILE_B + li * 16;                  \
        const u32 _d = sb + (buf) * STAGE_B + dstBase;                        \
        _Pragma("unroll")                                                     \
        for (int _k = 0; _k < 8; ++_k) cp16(_d + _k * 2048, _src + _k * 2048);\
    } while (0)

    G_ISSUE(0, 0); cp_commit();
    G_ISSUE(1, 1); cp_commit();

    float acc[4][4][4] = {};
    int buf = 0;
    #pragma unroll 1
    for (int s = 0; s < 16; ++s) {
        cp_wait1();
        __syncthreads();
        int b2 = buf + 2; if (b2 >= 3) b2 -= 3;
        if (s + 2 < 16) G_ISSUE(s + 2, b2);
        cp_commit();
        stage_mma(sb + buf * STAGE_B, tid, acc);
        if (++buf == 3) buf = 0;
    }
    #undef G_ISSUE

    // ---- epilogue: stage z in smem; coalesced Z store; split-z emit (ping-pong)
    cp_wait0();
    __syncthreads();

    float* zs = (float*)smc;                          // [128][132] = 67584 B
    char*  scr0 = smc + 67584;                        // 16 KB
    char*  scr1 = scr0 + TILE_B;                      // 16 KB
    const int lane = tid & 31, w = tid >> 5;
    const int mw = w >> 2, nw = w & 3;
    const int row0 = rb * 128, col0 = ct * 128;

    #pragma unroll
    for (int nb = 0; nb < 4; ++nb) {
        const int cb = nw * 32 + nb * 8 + (lane & 3) * 2;
        const float2 bv = *(const float2*)&bias[col0 + cb];
        #pragma unroll
        for (int mb = 0; mb < 4; ++mb) {
            const int rr = mw * 64 + mb * 16 + (lane >> 2);
            *(float2*)&zs[rr * 132 + cb] =
                make_float2(acc[mb][nb][0] + bv.x, acc[mb][nb][1] + bv.y);
            *(float2*)&zs[(rr + 8) * 132 + cb] =
                make_float2(acc[mb][nb][2] + bv.x, acc[mb][nb][3] + bv.y);
        }
    }
    __syncthreads();

    // coalesced fp32 Z store
    #pragma unroll
    for (int it = 0; it < 16; ++it) {
        const int idx = tid + it * 256;               // 4096 float4 slots
        const int rr = idx >> 5, c4 = (idx & 31) * 4;
        float4 v = *(float4*)&zs[rr * 132 + c4];
        *(float4*)&Z[(size_t)(row0 + rr) * D + col0 + c4] = v;
    }

    // split-z emit: ping-pong scratch, 5 syncs, STG(sl) overlaps split(sl+1)
    const int r = tid >> 1, h = tid & 1, e = r & 7;
    char* zdstBase = &g_zsplit[rb][ct * 4][0];

    {   // prime slice 0
        float4 v[4];
        #pragma unroll
        for (int i = 0; i < 4; ++i) v[i] = *(float4*)&zs[r * 132 + h * 16 + i * 4];
        split16(v, scr0 + r * 128, h * 2, e);
    }
    __syncthreads();
    #pragma unroll 1
    for (int sl = 0; sl < 4; ++sl) {
        char* cur = (sl & 1) ? scr1 : scr0;
        char* nxt = (sl & 1) ? scr0 : scr1;
        char* dst = zdstBase + sl * TILE_B;
        #pragma unroll
        for (int k = 0; k < 4; ++k)
            *(uint4*)(dst + tid * 16 + k * 4096) =
                *(const uint4*)(cur + tid * 16 + k * 4096);
        if (sl < 3) {
            float4 v[4];
            #pragma unroll
            for (int i = 0; i < 4; ++i)
                v[i] = *(float4*)&zs[r * 132 + (sl + 1) * 32 + h * 16 + i * 4];
            split16(v, nxt + r * 128, h * 2, e);
        }
        __syncthreads();
    }
}

// ---------------------------------------------------------------- VQ: dots, argmin, gather
__global__ void __launch_bounds__(256, 2)
vq_hmma(const float* __restrict__ CB, float* __restrict__ Q1, float* __restrict__ Q2)
{
    extern __shared__ char smc[];
    float* scn  = (float*)(smc + LOOP_SMEM);
    ull*   wb   = (ull*)  (smc + LOOP_SMEM + 512);
    int*   bidx = (int*)  (smc + LOOP_SMEM + 512 + 4096);

    const u32 sb = smem_u32(smc);
    const int tid = threadIdx.x;
    const int rb = blockIdx.x;
    const int row0 = rb * 128;
    if (tid < NC) scn[tid] = g_cnorm[tid];

    const int li = tid & 127;
    const char* srcBase = (tid < 128) ? &g_zsplit[rb][0][0] : &g_cbsplit[0][0];
    const u32 dstBase = ((tid < 128) ? 0u : (u32)TILE_B) + li * 16;

    #define V_ISSUE(s, buf) do {                                              \
        const char* _src = srcBase + (s) * TILE_B + li * 16;                  \
        const u32 _d = sb + (buf) * STAGE_B + dstBase;                        \
        _Pragma("unroll")                                                     \
        for (int _k = 0; _k < 8; ++_k) cp16(_d + _k * 2048, _src + _k * 2048);\
    } while (0)

    V_ISSUE(0, 0); cp_commit();
    V_ISSUE(1, 1); cp_commit();

    float acc[4][4][4] = {};
    int buf = 0;
    #pragma unroll 1
    for (int s = 0; s < 16; ++s) {
        cp_wait1();
        __syncthreads();
        int b2 = buf + 2; if (b2 >= 3) b2 -= 3;
        if (s + 2 < 16) V_ISSUE(s + 2, b2);
        cp_commit();
        stage_mma(sb + buf * STAGE_B, tid, acc);
        if (++buf == 3) buf = 0;
    }
    #undef V_ISSUE

    const int lane = tid & 31, w = tid >> 5;
    const int mw = w >> 2, nw = w & 3;

    #pragma unroll
    for (int mb = 0; mb < 4; ++mb) {
        #pragma unroll
        for (int rh = 0; rh < 2; ++rh) {
            ull best = ~0ull;
            #pragma unroll
            for (int nb = 0; nb < 4; ++nb) {
                #pragma unroll
                for (int j = 0; j < 2; ++j) {
                    const int code = nw * 32 + nb * 8 + (lane & 3) * 2 + j;
                    const float sc = fmaf(-2.f, acc[mb][nb][rh * 2 + j], scn[code]);
                    u32 o = __float_as_uint(sc);
                    o = (o & 0x80000000u) ? ~o : (o | 0x80000000u);
                    const ull key = ((ull)o << 32) | (u32)code;
                    if (key < best) best = key;
                }
            }
            ull t = __shfl_xor_sync(0xffffffffu, best, 1); if (t < best) best = t;
            t     = __shfl_xor_sync(0xffffffffu, best, 2); if (t < best) best = t;
            const int rowl = mw * 64 + mb * 16 + rh * 8 + (lane >> 2);
            if ((lane & 3) == 0) wb[rowl * 4 + nw] = best;
        }
    }
    __syncthreads();

    if (tid < 128) {
        ull m = wb[tid * 4];
        ull a = wb[tid * 4 + 1]; if (a < m) m = a;
        a = wb[tid * 4 + 2];     if (a < m) m = a;
        a = wb[tid * 4 + 3];     if (a < m) m = a;
        bidx[tid] = (int)(m & 0xffffffffu);
    }
    __syncthreads();

    for (int rr = w; rr < 128; rr += 8) {
        const int idx = bidx[rr];
        const float4* s4 = (const float4*)(CB + (size_t)idx * D);
        float4* o1 = (float4*)(Q1 + (size_t)(row0 + rr) * D);
        float4* o2 = (float4*)(Q2 + (size_t)(row0 + rr) * D);
        #pragma unroll
        for (int i = lane; i < D / 4; i += 32) {
            const float4 vv = s4[i];
            o1[i] = vv;
            o2[i] = vv;
        }
    }
}

// ---------------------------------------------------------------- launcher
extern "C" void kernel_launch(void* const* d_in, const int* in_sizes, int n_in,
                              void* d_out, int out_size)
{
    const float* x  = (const float*)d_in[0];
    const float* W  = (const float*)d_in[1];
    const float* b  = (const float*)d_in[2];
    const float* cb = (const float*)d_in[3];

    const int M = in_sizes[0] / D;            // 32768

    float* out = (float*)d_out;
    float* q1 = out;
    float* q2 = out + (size_t)M * D;
    float* z  = out + (size_t)2 * M * D;

    prepass_kernel<<<(M / 128) * 16 + 81, 256>>>(x, W, cb);

    cudaFuncSetAttribute(gemm_hmma, cudaFuncAttributeMaxDynamicSharedMemorySize, GEMM_SMEM);
    gemm_hmma<<<dim3(D / 128, M / 128), 256, GEMM_SMEM>>>(b, z);

    cudaFuncSetAttribute(vq_hmma, cudaFuncAttributeMaxDynamicSharedMemorySize, VQ_SMEM);
    vq_hmma<<<M / 128, 256, VQ_SMEM>>>(cb, q1, q2);
}